// round 3
// baseline (speedup 1.0000x reference)
#include <cuda_runtime.h>
#include <math.h>

// ---- model constants ----
#define B_SZ    16384
#define N_BAS   32
#define T_STEPS 300
#define HIDN    64
#define M_TOT   (B_SZ * 2)          // 32768 channels
#define DT_F    (1.0f / 300.0f)

// scratch (static device globals — allocation-free)
__device__ float g_coef[T_STEPS * N_BAS];   // [t][n]  coef = x*psi/sum(psi)
__device__ float g_wM[M_TOT * N_BAS];       // [m][n]  raw basis weights
__device__ float g_goal[M_TOT];
__device__ float g_az[M_TOT];
__device__ float g_val[M_TOT];

// ---------------------------------------------------------------------------
// coef[t][n] = x_{t+1} * psi_{t+1}[n] / sum(psi_{t+1})   (batch-independent)
__global__ void coef_kernel(const float* __restrict__ c,
                            const float* __restrict__ s2) {
    int t = blockIdx.x * blockDim.x + threadIdx.x;
    if (t >= T_STEPS) return;
    float x = powf(1.0f - DT_F, (float)(t + 1));
    float psi[N_BAS];
    float sum = 0.0f;
#pragma unroll
    for (int n = 0; n < N_BAS; n++) {
        float dx = x - c[n];
        float p = expf(-0.5f * dx * dx / s2[n]);
        psi[n] = p;
        sum += p;
    }
    float inv = x / sum;
#pragma unroll
    for (int n = 0; n < N_BAS; n++) g_coef[t * N_BAS + n] = psi[n] * inv;
}

// ---------------------------------------------------------------------------
// params: block = 256 threads = 64 channels x 4 output-groups. 512 blocks.
// Each thread: 8 basis-weight outputs + 1 special (goal / az / sigma / value).
__global__ __launch_bounds__(256)
void params_kernel(const float* __restrict__ state,
                   const float* __restrict__ fc1_w, const float* __restrict__ fc1_b,
                   const float* __restrict__ fc2m_w, const float* __restrict__ fc2m_b,
                   const float* __restrict__ sig_w, const float* __restrict__ sig_b,
                   const float* __restrict__ val_w, const float* __restrict__ val_b,
                   float* __restrict__ outS) {
    __shared__ float hs[32 * 65];        // h, pitch 65 (conflict-free)
    __shared__ float w2i[32 * 128];      // W2 rows 2..65 interleaved [o][j*2+d]
    __shared__ float gli[128];           // goal rows interleaved [j*2+d]
    __shared__ float azi[128];           // az row duplicated for both d
    __shared__ float sgi[128];           // sigma rows interleaved
    __shared__ float vli[128];           // value rows interleaved
    __shared__ float b2s[66];
    __shared__ float sbs[2], vbs[2];
    __shared__ float ws[64 * 33];        // wM staging, pitch 33

    const int tid = threadIdx.x;
    const int b0 = blockIdx.x * 32;

    // stage weights (coalesced global reads, scattered smem writes)
    for (int i = tid; i < 64 * 64; i += 256) {   // rows 2..65
        int r = i >> 6, j = i & 63;              // r = d*32 + o
        int dd = r >> 5, o = r & 31;
        w2i[o * 128 + j * 2 + dd] = fc2m_w[(2 + r) * 64 + j];
    }
    for (int i = tid; i < 128; i += 256) {
        int dd = i & 1, j = i >> 1;
        gli[j * 2 + dd] = fc2m_w[dd * 64 + j];
        sgi[j * 2 + dd] = sig_w[dd * 64 + j];
        vli[j * 2 + dd] = val_w[dd * 64 + j];
        azi[j * 2 + dd] = fc2m_w[65 * 64 + j];
    }
    for (int i = tid; i < 66; i += 256) b2s[i] = fc2m_b[i];
    if (tid < 2) { sbs[tid] = sig_b[tid]; vbs[tid] = val_b[tid]; }

    // hidden layer for 32 batch rows: h = tanh(state @ W1^T + b1) * 0.1
    for (int e = tid; e < 32 * 64; e += 256) {
        int bl = e >> 6, j = e & 63;
        const float* st = state + (size_t)(b0 + bl) * 3;
        float a = fmaf(__ldg(st + 0), __ldg(fc1_w + j * 3 + 0),
                  fmaf(__ldg(st + 1), __ldg(fc1_w + j * 3 + 1),
                  fmaf(__ldg(st + 2), __ldg(fc1_w + j * 3 + 2), __ldg(fc1_b + j))));
        hs[bl * 65 + j] = tanhf(a) * 0.1f;
    }
    __syncthreads();

    const int c  = tid & 63;     // local channel
    const int og = tid >> 6;     // output group 0..3 (uniform per warp)
    const int d  = c & 1;
    const int m  = blockIdx.x * 64 + c;
    const float* hrow = &hs[(c >> 1) * 65];
    const float* sprow = (og == 0) ? gli : (og == 1) ? azi : (og == 2) ? sgi : vli;

    float acc[9];
#pragma unroll
    for (int k = 0; k < 9; k++) acc[k] = 0.f;

#pragma unroll 8
    for (int j = 0; j < 64; j++) {
        const float hv = hrow[j];
        const int ji = j * 2 + d;
#pragma unroll
        for (int k = 0; k < 8; k++)
            acc[k] = fmaf(hv, w2i[(og + 4 * k) * 128 + ji], acc[k]);
        acc[8] = fmaf(hv, sprow[ji], acc[8]);
    }

#pragma unroll
    for (int k = 0; k < 8; k++) {
        const int o = og + 4 * k;
        ws[c * 33 + o] = acc[k] + b2s[2 + d * 32 + o];
    }
    if (og == 0)      g_goal[m] = acc[8] + b2s[d];
    else if (og == 1) g_az[m] = fminf(fmaxf(acc[8] + b2s[65], 0.5f), 30.0f);
    else if (og == 2) outS[m] = 1.0f / (1.0f + expf(-(acc[8] + sbs[d]))) + 0.001f;
    else              g_val[m] = acc[8] + vbs[d];
    __syncthreads();

    // coalesced wM store
    const int mbase = blockIdx.x * 64;
    for (int i = tid; i < 64 * 32; i += 256) {
        int ml = i >> 5, o = i & 31;
        g_wM[(size_t)(mbase + ml) * 32 + o] = ws[ml * 33 + o];
    }
}

// ---------------------------------------------------------------------------
// fused forcing + rollout: block = 256 threads = 64 channels x 4 t-slices.
// Threads j=0..3 of a channel compute the (t-parallel) forcing dots for
// their 7-8 steps of the 30-step chunk; thread j=0 runs the sequential
// recurrence; whole warp does the coalesced writeback. 512 blocks.
__global__ __launch_bounds__(256)
void roll_kernel(const float* __restrict__ state, float* __restrict__ outA) {
    __shared__ float fs[8][8 * 31];
    __shared__ float as[8][8 * 31];

    const int tid  = threadIdx.x;
    const int lane = tid & 31;
    const int warp = tid >> 5;
    const int c = lane >> 2;          // channel within warp (0..7)
    const int j = lane & 3;           // t-slice
    const int m = blockIdx.x * 64 + warp * 8 + c;

    float w[N_BAS];
#pragma unroll
    for (int q = 0; q < 8; q++) {
        float4 v = __ldg((const float4*)&g_wM[(size_t)m * 32] + q);
        w[4 * q + 0] = v.x; w[4 * q + 1] = v.y;
        w[4 * q + 2] = v.z; w[4 * q + 3] = v.w;
    }
    const float goal = __ldg(&g_goal[m]);
    const float az   = __ldg(&g_az[m]);
    const float y0   = __ldg(&state[(size_t)(m >> 1) * 3 + (m & 1)]);
    const float G  = goal - y0;
    const float bz = az * 0.25f;
    float y = y0, z = 0.01f;

    float* fw = fs[warp];
    float* aw = as[warp];
    const int s_lo = j * 8;
    const int mw = blockIdx.x * 64 + warp * 8;

    for (int ch = 0; ch < 10; ch++) {
        const int t0 = ch * 30;
#pragma unroll
        for (int k = 0; k < 8; k++) {
            const int s = s_lo + k;
            if (s < 30) {
                const float4* cf = (const float4*)&g_coef[(t0 + s) * N_BAS];
                float a0 = 0.f, a1 = 0.f, a2 = 0.f, a3 = 0.f;
#pragma unroll
                for (int i = 0; i < 8; i++) {
                    float4 f = __ldg(cf + i);
                    a0 = fmaf(w[4 * i + 0], f.x, a0);
                    a1 = fmaf(w[4 * i + 1], f.y, a1);
                    a2 = fmaf(w[4 * i + 2], f.z, a2);
                    a3 = fmaf(w[4 * i + 3], f.w, a3);
                }
                fw[c * 31 + s] = (a0 + a1) + (a2 + a3);
            }
        }
        __syncwarp();
        if (j == 0) {
#pragma unroll
            for (int s = 0; s < 30; s++) {
                aw[c * 31 + s] = z * DT_F;    // a[t] = Y[t+1]-Y[t] = z_t*DT
                const float dz = fmaf(az, fmaf(bz, goal - y, -z), G * fw[c * 31 + s]);
                y = fmaf(z, DT_F, y);
                z = fmaf(dz, DT_F, z);
            }
        }
        __syncwarp();
#pragma unroll
        for (int i = lane; i < 240; i += 32) {
            const int r = i / 30, col = i - r * 30;
            outA[(size_t)(mw + r) * 300 + t0 + col] = aw[r * 31 + col];
        }
        __syncwarp();
    }
}

// ---------------------------------------------------------------------------
// value broadcast: pure streaming float4 writes, one wave of 76K warps.
__global__ __launch_bounds__(256)
void value_kernel(float4* __restrict__ outV4) {
    const int idx = blockIdx.x * 256 + threadIdx.x;   // m*75 + seg
    const int m = idx / 75;
    const float v = __ldg(&g_val[m]);
    outV4[idx] = make_float4(v, v, v, v);
}

// ---------------------------------------------------------------------------
extern "C" void kernel_launch(void* const* d_in, const int* in_sizes, int n_in,
                              void* d_out, int out_size) {
    const float* state  = (const float*)d_in[0];
    const float* fc1_w  = (const float*)d_in[1];
    const float* fc1_b  = (const float*)d_in[2];
    const float* fc2m_w = (const float*)d_in[3];
    const float* fc2m_b = (const float*)d_in[4];
    const float* sig_w  = (const float*)d_in[5];
    const float* sig_b  = (const float*)d_in[6];
    const float* val_w  = (const float*)d_in[7];
    const float* val_b  = (const float*)d_in[8];
    const float* dmp_c  = (const float*)d_in[9];
    const float* dmp_s2 = (const float*)d_in[10];

    float* out = (float*)d_out;
    float* outA = out;                               // [B,2,300]
    float* outS = out + (size_t)M_TOT * T_STEPS;     // [B,2,1]
    float* outV = outS + M_TOT;                      // [B,2,300]

    coef_kernel<<<1, 320>>>(dmp_c, dmp_s2);
    params_kernel<<<M_TOT / 64, 256>>>(state, fc1_w, fc1_b, fc2m_w, fc2m_b,
                                       sig_w, sig_b, val_w, val_b, outS);
    roll_kernel<<<M_TOT / 64, 256>>>(state, outA);
    value_kernel<<<(M_TOT * 75) / 256, 256>>>((float4*)outV);
}

// round 5
// speedup vs baseline: 2.7714x; 2.7714x over previous
#include <cuda_runtime.h>
#include <math.h>

// ---- model constants ----
#define B_SZ    16384
#define N_BAS   32
#define T_STEPS 300
#define HIDN    64
#define M_TOT   (B_SZ * 2)          // 32768 channels
#define DT_F    (1.0f / 300.0f)

// scratch (static device globals — allocation-free)
__device__ float g_coef[T_STEPS * N_BAS];   // [t][n]  coef = x*psi/sum(psi)
__device__ float g_wT[N_BAS * M_TOT];       // [n][m]  G-prescaled basis weights
__device__ float g_goal[M_TOT];
__device__ float g_az[M_TOT];
__device__ float g_val[M_TOT];
__device__ float g_F[T_STEPS * M_TOT];      // [t][m]  forcing term

// ---------------------------------------------------------------------------
// coef[t][n] = x_{t+1} * psi_{t+1}[n] / sum(psi_{t+1})   (batch-independent)
__global__ void coef_kernel(const float* __restrict__ c,
                            const float* __restrict__ s2) {
    int t = blockIdx.x * blockDim.x + threadIdx.x;
    if (t >= T_STEPS) return;
    float x = powf(1.0f - DT_F, (float)(t + 1));
    float psi[N_BAS];
    float sum = 0.0f;
#pragma unroll
    for (int n = 0; n < N_BAS; n++) {
        float dx = x - c[n];
        float p = expf(-0.5f * dx * dx / s2[n]);
        psi[n] = p;
        sum += p;
    }
    float inv = x / sum;
#pragma unroll
    for (int n = 0; n < N_BAS; n++) g_coef[t * N_BAS + n] = psi[n] * inv;
}

// ---------------------------------------------------------------------------
// params: block = 256 threads = 64 channels x 4 output-groups. 512 blocks.
__global__ __launch_bounds__(256)
void params_kernel(const float* __restrict__ state,
                   const float* __restrict__ fc1_w, const float* __restrict__ fc1_b,
                   const float* __restrict__ fc2m_w, const float* __restrict__ fc2m_b,
                   const float* __restrict__ sig_w, const float* __restrict__ sig_b,
                   const float* __restrict__ val_w, const float* __restrict__ val_b,
                   float* __restrict__ outS) {
    __shared__ float hs[32 * 65];
    __shared__ float w2i[32 * 128];
    __shared__ float gli[128];
    __shared__ float azi[128];
    __shared__ float sgi[128];
    __shared__ float vli[128];
    __shared__ float b2s[66];
    __shared__ float sbs[2], vbs[2];
    __shared__ float ws[64 * 33];
    __shared__ float sgoal[64];

    const int tid = threadIdx.x;
    const int b0 = blockIdx.x * 32;

    for (int i = tid; i < 64 * 64; i += 256) {
        int r = i >> 6, j = i & 63;
        int dd = r >> 5, o = r & 31;
        w2i[o * 128 + j * 2 + dd] = fc2m_w[(2 + r) * 64 + j];
    }
    for (int i = tid; i < 128; i += 256) {
        int dd = i & 1, j = i >> 1;
        gli[j * 2 + dd] = fc2m_w[dd * 64 + j];
        sgi[j * 2 + dd] = sig_w[dd * 64 + j];
        vli[j * 2 + dd] = val_w[dd * 64 + j];
        azi[j * 2 + dd] = fc2m_w[65 * 64 + j];
    }
    for (int i = tid; i < 66; i += 256) b2s[i] = fc2m_b[i];
    if (tid < 2) { sbs[tid] = sig_b[tid]; vbs[tid] = val_b[tid]; }

    for (int e = tid; e < 32 * 64; e += 256) {
        int bl = e >> 6, j = e & 63;
        const float* st = state + (size_t)(b0 + bl) * 3;
        float a = fmaf(__ldg(st + 0), __ldg(fc1_w + j * 3 + 0),
                  fmaf(__ldg(st + 1), __ldg(fc1_w + j * 3 + 1),
                  fmaf(__ldg(st + 2), __ldg(fc1_w + j * 3 + 2), __ldg(fc1_b + j))));
        hs[bl * 65 + j] = tanhf(a) * 0.1f;
    }
    __syncthreads();

    const int c  = tid & 63;
    const int og = tid >> 6;
    const int d  = c & 1;
    const int m  = blockIdx.x * 64 + c;
    const float* hrow = &hs[(c >> 1) * 65];
    const float* sprow = (og == 0) ? gli : (og == 1) ? azi : (og == 2) ? sgi : vli;

    float acc[9];
#pragma unroll
    for (int k = 0; k < 9; k++) acc[k] = 0.f;

#pragma unroll 8
    for (int j = 0; j < 64; j++) {
        const float hv = hrow[j];
        const int ji = j * 2 + d;
#pragma unroll
        for (int k = 0; k < 8; k++)
            acc[k] = fmaf(hv, w2i[(og + 4 * k) * 128 + ji], acc[k]);
        acc[8] = fmaf(hv, sprow[ji], acc[8]);
    }

#pragma unroll
    for (int k = 0; k < 8; k++) {
        const int o = og + 4 * k;
        ws[c * 33 + o] = acc[k] + b2s[2 + d * 32 + o];
    }
    if (og == 0) { float gl = acc[8] + b2s[d]; sgoal[c] = gl; g_goal[m] = gl; }
    else if (og == 1) g_az[m] = fminf(fmaxf(acc[8] + b2s[65], 0.5f), 30.0f);
    else if (og == 2) outS[m] = 1.0f / (1.0f + expf(-(acc[8] + sbs[d]))) + 0.001f;
    else              g_val[m] = acc[8] + vbs[d];
    __syncthreads();

    // coalesced transposed + G-prescaled store: g_wT[o][m] = w * (goal - y0)
    const int mbase = blockIdx.x * 64;
    for (int i = tid; i < 64 * 32; i += 256) {
        int o = i >> 6, ml = i & 63;
        const int mm = mbase + ml;
        const float y0 = __ldg(&state[(size_t)(mm >> 1) * 3 + (mm & 1)]);
        g_wT[(size_t)o * M_TOT + mm] = ws[ml * 33 + o] * (sgoal[ml] - y0);
    }
}

// ---------------------------------------------------------------------------
// GEMM: F[t][m] = sum_n wT[n][m] * coef[t][n]  (coef staged in smem)
__global__ __launch_bounds__(128)
void gemm_kernel() {
    __shared__ float sc[30 * N_BAS];

    const int tid = threadIdx.x;
    const int m = blockIdx.x * 128 + tid;
    const int t0 = blockIdx.y * 30;

    for (int i = tid; i < 30 * N_BAS; i += 128) sc[i] = g_coef[t0 * N_BAS + i];
    __syncthreads();

    float w[N_BAS];
#pragma unroll
    for (int n = 0; n < N_BAS; n++) w[n] = g_wT[(size_t)n * M_TOT + m];

#pragma unroll
    for (int s = 0; s < 30; s++) {
        const float4* cf = (const float4*)&sc[s * N_BAS];
        float a0 = 0.f, a1 = 0.f, a2 = 0.f, a3 = 0.f;
#pragma unroll
        for (int i = 0; i < 8; i++) {
            float4 f = cf[i];
            a0 = fmaf(w[4 * i + 0], f.x, a0);
            a1 = fmaf(w[4 * i + 1], f.y, a1);
            a2 = fmaf(w[4 * i + 2], f.z, a2);
            a3 = fmaf(w[4 * i + 3], f.w, a3);
        }
        g_F[(size_t)(t0 + s) * M_TOT + m] = (a0 + a1) + (a2 + a3);
    }
}

// ---------------------------------------------------------------------------
// rollout via linear-recurrence chunk decomposition.
// Block = 320 threads: warp w <-> chunk w (30 steps), lane <-> channel.
// M = rI + DT*N with N nilpotent (bz = az/4 -> critical damping), so
// M^30 = r^30 I + 30 r^29 DT N exactly. Chunks become independent after a
// tiny boundary scan.
__global__ __launch_bounds__(320)
void roll_kernel(const float* __restrict__ state,
                 float* __restrict__ outA, float* __restrict__ outV) {
    __shared__ float aggU[10][32];
    __shared__ float aggZ[10][32];
    __shared__ float tile[10][32 * 17];   // 16-col half-tiles, pitch 17

    const int lane = threadIdx.x & 31;
    const int w    = threadIdx.x >> 5;    // chunk index 0..9
    const int m0   = blockIdx.x * 32;
    const int m    = m0 + lane;
    const int t0   = w * 30;

    const float az   = __ldg(&g_az[m]);
    const float goal = __ldg(&g_goal[m]);
    const float y0   = __ldg(&state[(size_t)(m >> 1) * 3 + (m & 1)]);
    const float vv   = __ldg(&g_val[m]);
    const float azbz = az * az * 0.25f;   // az*bz

    // pass 1: forcing-only chunk response (zero init)
    float u = 0.f, z = 0.f;
#pragma unroll
    for (int s = 0; s < 30; s++) {
        const float f = __ldg(&g_F[(size_t)(t0 + s) * M_TOT + m]);
        const float dz = fmaf(-azbz, u, fmaf(-az, z, f));
        u = fmaf(z, DT_F, u);
        z = fmaf(dz, DT_F, z);
    }
    aggU[w][lane] = u;
    aggZ[w][lane] = z;
    __syncthreads();

    // closed-form M^30
    const float r  = 1.f - az * DT_F * 0.5f;
    const float r2 = r * r, r4 = r2 * r2, r8 = r4 * r4, r16 = r8 * r8;
    const float r29 = r16 * r8 * r4 * r;
    const float r30 = r29 * r;
    const float p = 30.f * r29 * DT_F;
    const float M11 = fmaf(p,  az * 0.5f, r30);
    const float M12 = p;
    const float M21 = -p * azbz;
    const float M22 = fmaf(-p, az * 0.5f, r30);

    // boundary state for this chunk (redundant short scan per warp)
    u = y0 - goal;
    z = 0.01f;
    for (int j = 0; j < w; j++) {
        const float nu = fmaf(M11, u, M12 * z) + aggU[j][lane];
        const float nz = fmaf(M21, u, M22 * z) + aggZ[j][lane];
        u = nu; z = nz;
    }

    // pass 2: expansion (f re-read hits L1/L2), transpose writeback in halves
    float* tl = tile[w];
#pragma unroll
    for (int half = 0; half < 2; half++) {
#pragma unroll
        for (int s = 0; s < 15; s++) {
            const int t = t0 + half * 15 + s;
            const float f = __ldg(&g_F[(size_t)t * M_TOT + m]);
            tl[lane * 17 + s] = z * DT_F;          // a[t] = z_t * DT
            const float dz = fmaf(-azbz, u, fmaf(-az, z, f));
            u = fmaf(z, DT_F, u);
            z = fmaf(dz, DT_F, z);
        }
        __syncwarp();
#pragma unroll
        for (int rr = 0; rr < 32; rr++) {
            if (lane < 15)
                outA[(size_t)(m0 + rr) * 300 + t0 + half * 15 + lane] =
                    tl[rr * 17 + lane];
        }
        __syncwarp();
    }

    // value broadcast for this chunk's 30 columns
#pragma unroll
    for (int rr = 0; rr < 32; rr++) {
        const float vr = __shfl_sync(0xffffffffu, vv, rr);
        if (lane < 30)
            outV[(size_t)(m0 + rr) * 300 + t0 + lane] = vr;
    }
}

// ---------------------------------------------------------------------------
extern "C" void kernel_launch(void* const* d_in, const int* in_sizes, int n_in,
                              void* d_out, int out_size) {
    const float* state  = (const float*)d_in[0];
    const float* fc1_w  = (const float*)d_in[1];
    const float* fc1_b  = (const float*)d_in[2];
    const float* fc2m_w = (const float*)d_in[3];
    const float* fc2m_b = (const float*)d_in[4];
    const float* sig_w  = (const float*)d_in[5];
    const float* sig_b  = (const float*)d_in[6];
    const float* val_w  = (const float*)d_in[7];
    const float* val_b  = (const float*)d_in[8];
    const float* dmp_c  = (const float*)d_in[9];
    const float* dmp_s2 = (const float*)d_in[10];

    float* out = (float*)d_out;
    float* outA = out;                               // [B,2,300]
    float* outS = out + (size_t)M_TOT * T_STEPS;     // [B,2,1]
    float* outV = outS + M_TOT;                      // [B,2,300]

    coef_kernel<<<10, 32>>>(dmp_c, dmp_s2);
    params_kernel<<<M_TOT / 64, 256>>>(state, fc1_w, fc1_b, fc2m_w, fc2m_b,
                                       sig_w, sig_b, val_w, val_b, outS);
    dim3 ggrid(M_TOT / 128, T_STEPS / 30);
    gemm_kernel<<<ggrid, 128>>>();
    roll_kernel<<<M_TOT / 32, 320>>>(state, outA, outV);
}